// round 11
// baseline (speedup 1.0000x reference)
#include <cuda_runtime.h>
#include <cuda_fp16.h>
#include <cstdint>

// Decoder LSTM: B=128, H=1024, T=256, OUT=1, IN=2.
// Persistent kernel, 128 CTAs x 512 thr (16 warps).
// 2D partition: CTA (bg, ng) owns batch rows [bg*64, bg*64+64) x hidden units
// [ng*16, ng*16+16)  (64 gate rows of W_hh in SMEM fp16, 132KB).
// Warp (rtp, nh, kq) = 2 rt-tiles x 32 N (nb parity nh) x k-quarter(256).
// gates via mma.m16n8k16 fp16->f32, single product; k-partials merged in SMEM.
// h broadcast = fp16 A-fragment buffer; each CTA reads only its batch half.

#define NCTA 128
#define NTHR 512
#define HID 1024
#define BSZ 128
#define KP 1032   // padded K stride (fp16 elems) for W in SMEM

#define W_BYTES (64 * KP * 2)
#define CONST_BYTES 1024
#define RED_BYTES (4 * 3 * 32 * 32 * 4)
#define SMEM_BYTES (W_BYTES + CONST_BYTES + RED_BYTES)

// h in A-fragment layout (fp16x2): [rt 0..7][kt 0..63][lane 0..31][reg 0..3]
__device__ uint32_t g_frag[2][8 * 64 * 32 * 4];
__device__ unsigned int g_bar_count = 0;
__device__ unsigned int g_bar_gen = 0;

__device__ __forceinline__ float sigf(float x) {
    return __fdividef(1.0f, 1.0f + __expf(-x));
}
__device__ __forceinline__ float tanh_f(float x) {
    return __fmaf_rn(2.0f, __fdividef(1.0f, 1.0f + __expf(-2.0f * x)), -1.0f);
}

__device__ __forceinline__ void mma_f16(float* c, const uint4& a, uint32_t b0, uint32_t b1) {
    asm volatile(
        "mma.sync.aligned.m16n8k16.row.col.f32.f16.f16.f32 "
        "{%0,%1,%2,%3},{%4,%5,%6,%7},{%8,%9},{%0,%1,%2,%3};\n"
        : "+f"(c[0]), "+f"(c[1]), "+f"(c[2]), "+f"(c[3])
        : "r"(a.x), "r"(a.y), "r"(a.z), "r"(a.w), "r"(b0), "r"(b1));
}

__device__ __forceinline__ void ldsm_x4(uint32_t& r0, uint32_t& r1, uint32_t& r2,
                                        uint32_t& r3, uint32_t saddr) {
    asm volatile("ldmatrix.sync.aligned.m8n8.x4.shared.b16 {%0,%1,%2,%3}, [%4];\n"
                 : "=r"(r0), "=r"(r1), "=r"(r2), "=r"(r3) : "r"(saddr));
}

__device__ __forceinline__ uint32_t packh2(float a, float b) {
    __half2 p = __floats2half2_rn(a, b);
    return *(uint32_t*)&p;
}

__device__ __forceinline__ void grid_barrier() {
    __threadfence();
    __syncthreads();
    if (threadIdx.x == 0) {
        volatile unsigned int* vgen = &g_bar_gen;
        unsigned int g = *vgen;
        unsigned int arrived = atomicAdd(&g_bar_count, 1u);
        if (arrived == NCTA - 1) {
            g_bar_count = 0;
            __threadfence();
            atomicExch(&g_bar_gen, g + 1u);
        } else {
            while (*vgen == g) {}
        }
        __threadfence();
    }
    __syncthreads();
}

extern __shared__ char smem_raw[];

__global__ __launch_bounds__(NTHR, 1) void decoder_kernel(
    const float* __restrict__ h0, const float* __restrict__ c0,
    const float* __restrict__ Wih, const float* __restrict__ Whh,
    const float* __restrict__ bih, const float* __restrict__ bhh,
    const float* __restrict__ Wlin, const float* __restrict__ blin,
    float* __restrict__ out, int T)
{
    __half* ws = (__half*)smem_raw;                       // [64][KP] W slice
    float* cc0 = (float*)(smem_raw + W_BYTES);            // bias (t=0)   [64]
    float* cc1 = cc0 + 64;                                // bias+Wih[:,1][64]
    float* wi0 = cc1 + 64;                                // Wih[:,0]     [64]
    float* wl  = wi0 + 64;                                // Wlin slice   [16]
    float* red = (float*)(smem_raw + W_BYTES + CONST_BYTES); // [4][3][32][32]

    const int cta  = blockIdx.x;
    const int bg   = cta & 1;        // batch half
    const int ng   = cta >> 1;       // hidden group (16 units)
    const int tid  = threadIdx.x;
    const int w    = tid >> 5;
    const int rtp  = w & 1;          // rt-pair (2 tiles of 16 rows)
    const int nh   = (w >> 1) & 1;   // N half (nb parity)
    const int kq   = w >> 2;         // k quarter
    const int lane = tid & 31;
    const int gi   = lane >> 2;
    const int tq   = lane & 3;

    // ---------------- init: W slice (64 gate rows) -> SMEM fp16 ----------------
    // local row n = q*16 + v  ->  global gate row q*1024 + ng*16 + v
    for (int idx = tid; idx < 64 * HID; idx += NTHR) {
        int n = idx >> 10;
        int k = idx & (HID - 1);
        int row = ((n >> 4) << 10) + (ng << 4) + (n & 15);
        ws[n * KP + k] = __float2half_rn(Whh[row * HID + k]);
    }
    if (tid < 64) {
        int n = tid;
        int row = ((n >> 4) << 10) + (ng << 4) + (n & 15);
        float bb = bih[row] + bhh[row];
        cc0[n] = bb;
        cc1[n] = bb + Wih[row * 2 + 1];
        wi0[n] = Wih[row * 2 + 0];
    }
    if (tid < 16) wl[tid] = Wlin[(ng << 4) + tid];

    // h0 -> fragment buffer 0 (CTA c converts batch row c)
    for (int p = tid; p < HID / 2; p += NTHR) {
        int k0 = p << 1;
        float a = h0[cta * HID + k0], b = h0[cta * HID + k0 + 1];
        int rt = cta >> 4, kt = k0 >> 4;
        int lanep = (cta & 7) * 4 + ((k0 >> 1) & 3);
        int reg = ((cta >> 3) & 1) + 2 * ((k0 >> 3) & 1);
        g_frag[0][((rt * 64 + kt) * 32 + lanep) * 4 + reg] = packh2(a, b);
    }
    for (int t = tid; t < T; t += NTHR) out[cta * T + t] = 0.0f;

    // thread's rows (kq==0 warps do pointwise): base + rt_in*16 + rh*8 + gi
    const int rowbase = bg * 64 + rtp * 32;
    const int u0 = (ng << 4) + (nh << 3) + (tq << 1);   // global hidden unit

    float creg[2][4] = {{0.f,0.f,0.f,0.f},{0.f,0.f,0.f,0.f}};
    if (kq == 0) {
#pragma unroll
        for (int rt = 0; rt < 2; ++rt)
#pragma unroll
            for (int ci = 0; ci < 4; ++ci) {
                int row = rowbase + rt * 16 + (ci >> 1) * 8 + gi;
                creg[rt][ci] = c0[row * HID + u0 + (ci & 1)];
            }
    }
    const float blin0 = blin[0];

    // ldsm bases: 1st x4 = gates 0,1 (nb = nh, nh+2); 2nd = gates 2,3
    const int m_ = lane >> 3;
    const int r_ = lane & 7;
    const int wrow = (nh << 3) + ((m_ >> 1) << 4) + r_;   // local W row
    const int coff = (m_ & 1) << 3;
    const uint32_t s_w = (uint32_t)__cvta_generic_to_shared(ws);
    const uint32_t sb0 = s_w + (wrow * KP + coff) * 2;
    const uint32_t sb1 = sb0 + 32 * KP * 2;

    const int g_rt0  = bg * 4 + rtp * 2;                  // first global rt tile
    const int abase0 = g_rt0 * 8192 + (kq * 16) * 128 + lane * 4;
    const int abase1 = abase0 + 8192;
    float* redp = red + (((rtp * 2 + nh) * 3) * 32 + lane) * 32;   // +p*1024

    grid_barrier();

    // ---------------- time loop ----------------
    for (int t = 0; t < T; ++t) {
        const uint32_t* A = g_frag[t & 1];
        uint32_t* N = g_frag[(t + 1) & 1];

        // acc[rt][gate][cfrag]
        float acc0[4][4], acc1[4][4];
        if (kq == 0) {
            float op[2][2];
            const float* cc = cc0;
            if (t > 0) {
#pragma unroll
                for (int rt = 0; rt < 2; ++rt)
#pragma unroll
                    for (int rh = 0; rh < 2; ++rh)
                        op[rt][rh] = __ldcg(&out[(rowbase + rt*16 + rh*8 + gi) * T + t - 1]);
                cc = cc1;
            } else {
                op[0][0] = op[0][1] = op[1][0] = op[1][1] = 0.0f;
            }
#pragma unroll
            for (int g = 0; g < 4; ++g) {
                int n0 = g * 16 + (nh << 3) + (tq << 1);
                float b0 = cc[n0], b1 = cc[n0 + 1];
                float wa = wi0[n0], wb = wi0[n0 + 1];
#pragma unroll
                for (int ci = 0; ci < 4; ++ci) {
                    float bb = (ci & 1) ? b1 : b0;
                    float ww = (ci & 1) ? wb : wa;
                    acc0[g][ci] = fmaf(op[0][ci >> 1], ww, bb);
                    acc1[g][ci] = fmaf(op[1][ci >> 1], ww, bb);
                }
            }
        } else {
#pragma unroll
            for (int g = 0; g < 4; ++g)
#pragma unroll
                for (int ci = 0; ci < 4; ++ci) { acc0[g][ci] = 0.f; acc1[g][ci] = 0.f; }
        }

        // GEMM: this warp's 16 k-iters, 2 rt tiles x 4 gates
#pragma unroll 4
        for (int i = 0; i < 16; ++i) {
            uint4 a0 = __ldcg((const uint4*)(A + abase0 + i * 128));
            uint4 a1 = __ldcg((const uint4*)(A + abase1 + i * 128));
            uint32_t so = (kq * 16 + i) * 32;
            uint32_t b0, b1, b2, b3, b4, b5, b6, b7;
            ldsm_x4(b0, b1, b2, b3, sb0 + so);
            ldsm_x4(b4, b5, b6, b7, sb1 + so);
            mma_f16(acc0[0], a0, b0, b1);
            mma_f16(acc1[0], a1, b0, b1);
            mma_f16(acc0[1], a0, b2, b3);
            mma_f16(acc1[1], a1, b2, b3);
            mma_f16(acc0[2], a0, b4, b5);
            mma_f16(acc1[2], a1, b4, b5);
            mma_f16(acc0[3], a0, b6, b7);
            mma_f16(acc1[3], a1, b6, b7);
        }

        // merge k-quarter partials through SMEM
        if (kq > 0) {
            float* d = redp + (kq - 1) * 1024;
#pragma unroll
            for (int g = 0; g < 4; ++g) {
                *(float4*)(d + g * 4)      = *(float4*)acc0[g];
                *(float4*)(d + 16 + g * 4) = *(float4*)acc1[g];
            }
        }
        __syncthreads();

        if (kq == 0) {
#pragma unroll
            for (int p = 0; p < 3; ++p) {
                const float* s = redp + p * 1024;
#pragma unroll
                for (int g = 0; g < 4; ++g) {
                    float4 x = *(const float4*)(s + g * 4);
                    float4 y = *(const float4*)(s + 16 + g * 4);
                    acc0[g][0] += x.x; acc0[g][1] += x.y;
                    acc0[g][2] += x.z; acc0[g][3] += x.w;
                    acc1[g][0] += y.x; acc1[g][1] += y.y;
                    acc1[g][2] += y.z; acc1[g][3] += y.w;
                }
            }

            // pointwise LSTM update
            float hv[2][4];
#pragma unroll
            for (int ci = 0; ci < 4; ++ci) {
                {
                    float iv = sigf(acc0[0][ci]);
                    float fv = sigf(acc0[1][ci]);
                    float gv = tanh_f(acc0[2][ci]);
                    float ov = sigf(acc0[3][ci]);
                    float cn = fmaf(fv, creg[0][ci], iv * gv);
                    creg[0][ci] = cn;
                    hv[0][ci] = ov * tanh_f(cn);
                }
                {
                    float iv = sigf(acc1[0][ci]);
                    float fv = sigf(acc1[1][ci]);
                    float gv = tanh_f(acc1[2][ci]);
                    float ov = sigf(acc1[3][ci]);
                    float cn = fmaf(fv, creg[1][ci], iv * gv);
                    creg[1][ci] = cn;
                    hv[1][ci] = ov * tanh_f(cn);
                }
            }

            // h store: fragment index [rt_glob][kt=ng][lane gi*4+tq][reg rh+2nh]
#pragma unroll
            for (int rt = 0; rt < 2; ++rt) {
                int idx = (((g_rt0 + rt) * 64 + ng) * 32 + gi * 4 + tq) * 4 + 2 * nh;
                *(uint2*)(N + idx) =
                    make_uint2(packh2(hv[rt][0], hv[rt][1]),
                               packh2(hv[rt][2], hv[rt][3]));
            }

            // scalar head: s[rt][rh] = sum over this thread's 2 units
            float wa = wl[(nh << 3) + (tq << 1)];
            float wb = wl[(nh << 3) + (tq << 1) + 1];
            float s[2][2];
#pragma unroll
            for (int rt = 0; rt < 2; ++rt)
#pragma unroll
                for (int rh = 0; rh < 2; ++rh)
                    s[rt][rh] = hv[rt][rh * 2] * wa + hv[rt][rh * 2 + 1] * wb;
#pragma unroll
            for (int rt = 0; rt < 2; ++rt)
#pragma unroll
                for (int rh = 0; rh < 2; ++rh) {
                    s[rt][rh] += __shfl_xor_sync(0xffffffffu, s[rt][rh], 1);
                    s[rt][rh] += __shfl_xor_sync(0xffffffffu, s[rt][rh], 2);
                }
            if (tq == 0) {
                if (ng == 0 && nh == 0) {
                    s[0][0] += blin0; s[0][1] += blin0;
                    s[1][0] += blin0; s[1][1] += blin0;
                }
#pragma unroll
                for (int rt = 0; rt < 2; ++rt)
#pragma unroll
                    for (int rh = 0; rh < 2; ++rh) {
                        int row = rowbase + rt * 16 + rh * 8 + gi;
                        atomicAdd(&out[row * T + t], s[rt][rh]);
                    }
            }
        }

        grid_barrier();
    }
}

extern "C" void kernel_launch(void* const* d_in, const int* in_sizes, int n_in,
                              void* d_out, int out_size) {
    const float* h0   = (const float*)d_in[0];
    const float* c0   = (const float*)d_in[1];
    const float* Wih  = (const float*)d_in[2];
    const float* Whh  = (const float*)d_in[3];
    const float* bih  = (const float*)d_in[4];
    const float* bhh  = (const float*)d_in[5];
    const float* Wlin = (const float*)d_in[6];
    const float* blin = (const float*)d_in[7];
    float* out = (float*)d_out;

    int T = out_size / BSZ;
    if (T <= 0) return;

    cudaFuncSetAttribute(decoder_kernel,
                         cudaFuncAttributeMaxDynamicSharedMemorySize, SMEM_BYTES);
    decoder_kernel<<<NCTA, NTHR, SMEM_BYTES>>>(h0, c0, Wih, Whh, bih, bhh,
                                               Wlin, blin, out, T);
}

// round 13
// speedup vs baseline: 1.4326x; 1.4326x over previous
#include <cuda_runtime.h>
#include <cuda_fp16.h>
#include <cstdint>

// Decoder LSTM: B=128, H=1024, T=256, OUT=1, IN=2.
// Persistent kernel, 128 CTAs x 512 thr (16 warps).
// CTA (bg=cta&1, ng=cta>>1) owns batch rows [bg*64,+64) x hidden units
// [ng*16,+16): 64 gate rows of W_hh in SMEM fp16 (132KB).
// Warp (rt 0..3, kq 0..3): A block (rt, k-quarter) is unique per warp (no
// duplicated A reads). Per iter: 1 LDG.128 (A frag) + 4 LDSM.x4 (B, N=64)
// + 8 mma.m16n8k16 fp16->f32. 4-way k-partials merged via float4 SMEM.
// One grid barrier per step. h broadcast: fp16 A-fragment global buffer,
// each CTA reads only its 64-row batch half -> 16MB/step total.

#define NCTA 128
#define NTHR 512
#define HID 1024
#define BSZ 128
#define KP 1032   // padded K stride (fp16 elems) for W in SMEM

#define W_BYTES (64 * KP * 2)
#define CONST_BYTES 1024
#define RED_BYTES (4 * 3 * 8 * 32 * 16)
#define SMEM_BYTES (W_BYTES + CONST_BYTES + RED_BYTES)

// h in A-fragment layout (fp16x2): [rt 0..7][kt 0..63][lane 0..31][reg 0..3]
__device__ uint32_t g_frag[2][8 * 64 * 32 * 4];
__device__ unsigned int g_bar_count = 0;
__device__ unsigned int g_bar_gen = 0;

__device__ __forceinline__ float sigf(float x) {
    return __fdividef(1.0f, 1.0f + __expf(-x));
}
__device__ __forceinline__ float tanh_f(float x) {
    return __fmaf_rn(2.0f, __fdividef(1.0f, 1.0f + __expf(-2.0f * x)), -1.0f);
}

__device__ __forceinline__ void mma_f16(float* c, const uint4& a, uint32_t b0, uint32_t b1) {
    asm volatile(
        "mma.sync.aligned.m16n8k16.row.col.f32.f16.f16.f32 "
        "{%0,%1,%2,%3},{%4,%5,%6,%7},{%8,%9},{%0,%1,%2,%3};\n"
        : "+f"(c[0]), "+f"(c[1]), "+f"(c[2]), "+f"(c[3])
        : "r"(a.x), "r"(a.y), "r"(a.z), "r"(a.w), "r"(b0), "r"(b1));
}

__device__ __forceinline__ void ldsm_x4(uint32_t& r0, uint32_t& r1, uint32_t& r2,
                                        uint32_t& r3, uint32_t saddr) {
    asm volatile("ldmatrix.sync.aligned.m8n8.x4.shared.b16 {%0,%1,%2,%3}, [%4];\n"
                 : "=r"(r0), "=r"(r1), "=r"(r2), "=r"(r3) : "r"(saddr));
}

__device__ __forceinline__ uint32_t packh2(float a, float b) {
    __half2 p = __floats2half2_rn(a, b);
    return *(uint32_t*)&p;
}

__device__ __forceinline__ void grid_barrier() {
    __threadfence();
    __syncthreads();
    if (threadIdx.x == 0) {
        volatile unsigned int* vgen = &g_bar_gen;
        unsigned int g = *vgen;
        unsigned int arrived = atomicAdd(&g_bar_count, 1u);
        if (arrived == NCTA - 1) {
            g_bar_count = 0;
            __threadfence();
            atomicExch(&g_bar_gen, g + 1u);
        } else {
            while (*vgen == g) {}
        }
        __threadfence();
    }
    __syncthreads();
}

extern __shared__ char smem_raw[];

__global__ __launch_bounds__(NTHR, 1) void decoder_kernel(
    const float* __restrict__ h0, const float* __restrict__ c0,
    const float* __restrict__ Wih, const float* __restrict__ Whh,
    const float* __restrict__ bih, const float* __restrict__ bhh,
    const float* __restrict__ Wlin, const float* __restrict__ blin,
    float* __restrict__ out, int T)
{
    __half* ws = (__half*)smem_raw;                       // [64][KP] W slice
    float* cc0 = (float*)(smem_raw + W_BYTES);            // bias (t=0)    [64]
    float* cc1 = cc0 + 64;                                // bias+Wih[:,1] [64]
    float* wi0 = cc1 + 64;                                // Wih[:,0]      [64]
    float* wl  = wi0 + 64;                                // Wlin slice    [16]
    float* red = (float*)(smem_raw + W_BYTES + CONST_BYTES);

    const int cta  = blockIdx.x;
    const int bg   = cta & 1;        // batch half
    const int ng   = cta >> 1;       // hidden group (16 units)
    const int tid  = threadIdx.x;
    const int w    = tid >> 5;
    const int rt   = w & 3;          // rt tile within batch half
    const int kq   = w >> 2;         // k quarter
    const int lane = tid & 31;
    const int gi   = lane >> 2;
    const int tq   = lane & 3;

    // ---------------- init: W slice (64 gate rows) -> SMEM fp16 ----------------
    // local row n = g*16 + v  ->  global gate row g*1024 + ng*16 + v
    for (int idx = tid; idx < 64 * HID; idx += NTHR) {
        int n = idx >> 10;
        int k = idx & (HID - 1);
        int row = ((n >> 4) << 10) + (ng << 4) + (n & 15);
        ws[n * KP + k] = __float2half_rn(Whh[row * HID + k]);
    }
    if (tid < 64) {
        int n = tid;
        int row = ((n >> 4) << 10) + (ng << 4) + (n & 15);
        float bb = bih[row] + bhh[row];
        cc0[n] = bb;
        cc1[n] = bb + Wih[row * 2 + 1];
        wi0[n] = Wih[row * 2 + 0];
    }
    if (tid < 16) wl[tid] = Wlin[(ng << 4) + tid];

    // h0 -> fragment buffer 0 (CTA c converts batch row c)
    for (int p = tid; p < HID / 2; p += NTHR) {
        int k0 = p << 1;
        float a = h0[cta * HID + k0], b = h0[cta * HID + k0 + 1];
        int rtt = cta >> 4, kt = k0 >> 4;
        int lanep = (cta & 7) * 4 + ((k0 >> 1) & 3);
        int reg = ((cta >> 3) & 1) + 2 * ((k0 >> 3) & 1);
        g_frag[0][((rtt * 64 + kt) * 32 + lanep) * 4 + reg] = packh2(a, b);
    }
    for (int t = tid; t < T; t += NTHR) out[cta * T + t] = 0.0f;

    // this thread's rows (kq==0 warps do pointwise): bg*64 + rt*16 + rh*8 + gi
    const int rowbase = bg * 64 + rt * 16;

    // creg[rh][q], q = uh*2 + p, unit u = uh*8 + 2tq + p (local in 16)
    float creg[2][4] = {{0.f,0.f,0.f,0.f},{0.f,0.f,0.f,0.f}};
    if (kq == 0) {
#pragma unroll
        for (int rh = 0; rh < 2; ++rh)
#pragma unroll
            for (int q = 0; q < 4; ++q) {
                int u = (q >> 1) * 8 + (tq << 1) + (q & 1);
                creg[rh][q] = c0[(rowbase + rh * 8 + gi) * HID + (ng << 4) + u];
            }
    }
    const float blin0 = blin[0];

    // ldsm bases: group g2 covers n-tiles 2g2, 2g2+1 (W rows g2*16 .. +15)
    const int m_ = lane >> 3;
    const int r_ = lane & 7;
    const uint32_t s_w = (uint32_t)__cvta_generic_to_shared(ws);
    uint32_t sb[4];
#pragma unroll
    for (int g2 = 0; g2 < 4; ++g2) {
        int wrow = g2 * 16 + ((m_ >> 1) << 3) + r_;
        sb[g2] = s_w + (wrow * KP + ((m_ & 1) << 3)) * 2;
    }

    const int g_rt   = bg * 4 + rt;                       // global rt tile
    const int abase  = g_rt * 8192 + (kq << 4) * 128 + lane * 4;
    // reduce layout: [rt][kq-1][nb][lane] float4
    // offset(floats) = (((rt*3 + q)*8 + nb)*32 + lane)*4

    grid_barrier();

    // ---------------- time loop ----------------
    for (int t = 0; t < T; ++t) {
        const uint32_t* A = g_frag[t & 1];
        uint32_t* N = g_frag[(t + 1) & 1];

        // acc[nb][ci], nb = g*2 + uh, ci = rh*2 + p
        float acc[8][4];
        if (kq == 0) {
            float op[2];
            const float* cc = cc0;
            if (t > 0) {
                op[0] = __ldcg(&out[(rowbase + gi) * T + t - 1]);
                op[1] = __ldcg(&out[(rowbase + 8 + gi) * T + t - 1]);
                cc = cc1;
            } else {
                op[0] = op[1] = 0.0f;
            }
#pragma unroll
            for (int nb = 0; nb < 8; ++nb) {
                int g = nb >> 1, uh = nb & 1;
#pragma unroll
                for (int ci = 0; ci < 4; ++ci) {
                    int p = ci & 1, rh = ci >> 1;
                    int n = g * 16 + uh * 8 + (tq << 1) + p;
                    acc[nb][ci] = fmaf(op[rh], wi0[n], cc[n]);
                }
            }
        } else {
#pragma unroll
            for (int nb = 0; nb < 8; ++nb)
#pragma unroll
                for (int ci = 0; ci < 4; ++ci) acc[nb][ci] = 0.0f;
        }

        // GEMM: 16 k-iters, 16x64 tile per warp
#pragma unroll 4
        for (int i = 0; i < 16; ++i) {
            uint4 a = __ldcg((const uint4*)(A + abase + i * 128));
            uint32_t so = ((kq << 4) + i) * 32;
#pragma unroll
            for (int g2 = 0; g2 < 4; ++g2) {
                uint32_t b0, b1, b2, b3;
                ldsm_x4(b0, b1, b2, b3, sb[g2] + so);
                mma_f16(acc[2 * g2],     a, b0, b1);
                mma_f16(acc[2 * g2 + 1], a, b2, b3);
            }
        }

        // merge k-quarter partials through SMEM (float4, conflict-free)
        if (kq > 0) {
            float* d = red + (((rt * 3 + (kq - 1)) * 8) * 32 + lane) * 4;
#pragma unroll
            for (int nb = 0; nb < 8; ++nb)
                *(float4*)(d + nb * 128) = *(float4*)acc[nb];
        }
        __syncthreads();

        if (kq == 0) {
#pragma unroll
            for (int q = 0; q < 3; ++q) {
                const float* s = red + (((rt * 3 + q) * 8) * 32 + lane) * 4;
#pragma unroll
                for (int nb = 0; nb < 8; ++nb) {
                    float4 x = *(const float4*)(s + nb * 128);
                    acc[nb][0] += x.x; acc[nb][1] += x.y;
                    acc[nb][2] += x.z; acc[nb][3] += x.w;
                }
            }

            // pointwise LSTM: gates g for unit (uh,p) at acc[g*2+uh][rh*2+p]
            float hv[2][4];
#pragma unroll
            for (int rh = 0; rh < 2; ++rh)
#pragma unroll
                for (int q = 0; q < 4; ++q) {
                    int uh = q >> 1, p = q & 1;
                    int ci = rh * 2 + p;
                    float xi = acc[0 + uh][ci];
                    float xf = acc[2 + uh][ci];
                    float xg = acc[4 + uh][ci];
                    float xo = acc[6 + uh][ci];
                    float cn = fmaf(sigf(xf), creg[rh][q], sigf(xi) * tanh_f(xg));
                    creg[rh][q] = cn;
                    hv[rh][q] = sigf(xo) * tanh_f(cn);
                }

            // h store: one STG.128; reg(rh + 2uh) = pack(hv[rh][2uh], hv[rh][2uh+1])
            uint4 hp;
            hp.x = packh2(hv[0][0], hv[0][1]);
            hp.y = packh2(hv[1][0], hv[1][1]);
            hp.z = packh2(hv[0][2], hv[0][3]);
            hp.w = packh2(hv[1][2], hv[1][3]);
            *(uint4*)&N[((g_rt * 64 + ng) * 32 + lane) * 4] = hp;

            // scalar head
            float s[2];
#pragma unroll
            for (int rh = 0; rh < 2; ++rh) {
                float acc_s = 0.0f;
#pragma unroll
                for (int q = 0; q < 4; ++q) {
                    int u = (q >> 1) * 8 + (tq << 1) + (q & 1);
                    acc_s = fmaf(hv[rh][q], wl[u], acc_s);
                }
                acc_s += __shfl_xor_sync(0xffffffffu, acc_s, 1);
                acc_s += __shfl_xor_sync(0xffffffffu, acc_s, 2);
                s[rh] = acc_s;
            }
            if (tq == 0) {
                if (ng == 0) { s[0] += blin0; s[1] += blin0; }
                atomicAdd(&out[(rowbase + gi) * T + t], s[0]);
                atomicAdd(&out[(rowbase + 8 + gi) * T + t], s[1]);
            }
        }

        grid_barrier();
    }
}

extern "C" void kernel_launch(void* const* d_in, const int* in_sizes, int n_in,
                              void* d_out, int out_size) {
    const float* h0   = (const float*)d_in[0];
    const float* c0   = (const float*)d_in[1];
    const float* Wih  = (const float*)d_in[2];
    const float* Whh  = (const float*)d_in[3];
    const float* bih  = (const float*)d_in[4];
    const float* bhh  = (const float*)d_in[5];
    const float* Wlin = (const float*)d_in[6];
    const float* blin = (const float*)d_in[7];
    float* out = (float*)d_out;

    int T = out_size / BSZ;
    if (T <= 0) return;

    cudaFuncSetAttribute(decoder_kernel,
                         cudaFuncAttributeMaxDynamicSharedMemorySize, SMEM_BYTES);
    decoder_kernel<<<NCTA, NTHR, SMEM_BYTES>>>(h0, c0, Wih, Whh, bih, bhh,
                                               Wlin, blin, out, T);
}

// round 14
// speedup vs baseline: 1.5117x; 1.0552x over previous
#include <cuda_runtime.h>
#include <cuda_fp16.h>
#include <cstdint>

// Decoder LSTM: B=128, H=1024, T=256, OUT=1, IN=2.
// Persistent kernel, 128 CTAs x 256 thr (8 warps).
// CTA (bg=cta>>6, ng=cta&63) owns batch rows [bg*64,+64) x hidden units
// [ng*16,+16): 64 gate rows of W_hh in SMEM fp16 (132KB).
// Warp (rtp 0..1, kq 0..3): 2 rt tiles x 64 N x k-quarter. One B ldsm feeds
// BOTH rt tiles (halves LDSM traffic); each A block (rt,kq) read exactly once.
// 4-way k-partials merged via float4 SMEM. The two bg groups are fully
// independent -> separate 64-CTA grid barriers.

#define NCTA 128
#define NTHR 256
#define HID 1024
#define BSZ 128
#define KP 1032   // padded K stride (fp16 elems) for W in SMEM

#define W_BYTES (64 * KP * 2)
#define CONST_BYTES 1024
#define RED_BYTES (2 * 3 * 2 * 8 * 32 * 16)
#define SMEM_BYTES (W_BYTES + CONST_BYTES + RED_BYTES)

// h in A-fragment layout (fp16x2): [rt 0..7][kt 0..63][lane 0..31][reg 0..3]
__device__ uint32_t g_frag[2][8 * 64 * 32 * 4];
__device__ unsigned int g_bar_count[64];   // [grp*32], 128B apart
__device__ unsigned int g_bar_gen[64];

__device__ __forceinline__ float sigf(float x) {
    return __fdividef(1.0f, 1.0f + __expf(-x));
}
__device__ __forceinline__ float tanh_f(float x) {
    return __fmaf_rn(2.0f, __fdividef(1.0f, 1.0f + __expf(-2.0f * x)), -1.0f);
}

__device__ __forceinline__ void mma_f16(float* c, const uint4& a, uint32_t b0, uint32_t b1) {
    asm volatile(
        "mma.sync.aligned.m16n8k16.row.col.f32.f16.f16.f32 "
        "{%0,%1,%2,%3},{%4,%5,%6,%7},{%8,%9},{%0,%1,%2,%3};\n"
        : "+f"(c[0]), "+f"(c[1]), "+f"(c[2]), "+f"(c[3])
        : "r"(a.x), "r"(a.y), "r"(a.z), "r"(a.w), "r"(b0), "r"(b1));
}

__device__ __forceinline__ void ldsm_x4(uint32_t& r0, uint32_t& r1, uint32_t& r2,
                                        uint32_t& r3, uint32_t saddr) {
    asm volatile("ldmatrix.sync.aligned.m8n8.x4.shared.b16 {%0,%1,%2,%3}, [%4];\n"
                 : "=r"(r0), "=r"(r1), "=r"(r2), "=r"(r3) : "r"(saddr));
}

__device__ __forceinline__ uint32_t packh2(float a, float b) {
    __half2 p = __floats2half2_rn(a, b);
    return *(uint32_t*)&p;
}

// 64-CTA group barrier (two independent groups)
__device__ __forceinline__ void grid_barrier(int grp) {
    __threadfence();
    __syncthreads();
    if (threadIdx.x == 0) {
        volatile unsigned int* vgen = &g_bar_gen[grp * 32];
        unsigned int g = *vgen;
        unsigned int arrived = atomicAdd(&g_bar_count[grp * 32], 1u);
        if (arrived == 63) {
            g_bar_count[grp * 32] = 0;
            __threadfence();
            atomicExch((unsigned int*)&g_bar_gen[grp * 32], g + 1u);
        } else {
            while (*vgen == g) {}
        }
        __threadfence();
    }
    __syncthreads();
}

extern __shared__ char smem_raw[];

__global__ __launch_bounds__(NTHR, 1) void decoder_kernel(
    const float* __restrict__ h0, const float* __restrict__ c0,
    const float* __restrict__ Wih, const float* __restrict__ Whh,
    const float* __restrict__ bih, const float* __restrict__ bhh,
    const float* __restrict__ Wlin, const float* __restrict__ blin,
    float* __restrict__ out, int T)
{
    __half* ws = (__half*)smem_raw;                       // [64][KP] W slice
    float* cc0 = (float*)(smem_raw + W_BYTES);            // bias (t=0)    [64]
    float* cc1 = cc0 + 64;                                // bias+Wih[:,1] [64]
    float* wi0 = cc1 + 64;                                // Wih[:,0]      [64]
    float* wl  = wi0 + 64;                                // Wlin slice    [16]
    float* red = (float*)(smem_raw + W_BYTES + CONST_BYTES);

    const int cta  = blockIdx.x;
    const int bg   = cta >> 6;       // batch half / barrier group
    const int ng   = cta & 63;       // hidden group (16 units)
    const int tid  = threadIdx.x;
    const int w    = tid >> 5;
    const int rtp  = w & 1;          // rt pair (2 tiles of 16 rows)
    const int kq   = w >> 1;         // k quarter
    const int lane = tid & 31;
    const int gi   = lane >> 2;
    const int tq   = lane & 3;

    // ---------------- init: W slice (64 gate rows) -> SMEM fp16 ----------------
    for (int idx = tid; idx < 64 * HID; idx += NTHR) {
        int n = idx >> 10;
        int k = idx & (HID - 1);
        int row = ((n >> 4) << 10) + (ng << 4) + (n & 15);
        ws[n * KP + k] = __float2half_rn(Whh[row * HID + k]);
    }
    if (tid < 64) {
        int n = tid;
        int row = ((n >> 4) << 10) + (ng << 4) + (n & 15);
        float bb = bih[row] + bhh[row];
        cc0[n] = bb;
        cc1[n] = bb + Wih[row * 2 + 1];
        wi0[n] = Wih[row * 2 + 0];
    }
    if (tid < 16) wl[tid] = Wlin[(ng << 4) + tid];

    // h0 -> fragment buffer 0 (CTA c converts batch row c; row c is in half
    // c>>6 == this CTA's bg, so init stays within the barrier group)
    for (int p = tid; p < HID / 2; p += NTHR) {
        int k0 = p << 1;
        float a = h0[cta * HID + k0], b = h0[cta * HID + k0 + 1];
        int rtt = cta >> 4, kt = k0 >> 4;
        int lanep = (cta & 7) * 4 + ((k0 >> 1) & 3);
        int reg = ((cta >> 3) & 1) + 2 * ((k0 >> 3) & 1);
        g_frag[0][((rtt * 64 + kt) * 32 + lanep) * 4 + reg] = packh2(a, b);
    }
    for (int t = tid; t < T; t += NTHR) out[cta * T + t] = 0.0f;

    // this thread's rows (kq==0 warps do pointwise):
    //   row(r, rh) = bg*64 + (rtp*2 + r)*16 + rh*8 + gi
    const int rowbase = bg * 64 + (rtp << 5);

    // creg[r][rh*? ] -> creg[r][rh][? ] flattened: [2][2][4]
    float creg[2][2][4];
    if (kq == 0) {
#pragma unroll
        for (int r = 0; r < 2; ++r)
#pragma unroll
            for (int rh = 0; rh < 2; ++rh)
#pragma unroll
                for (int q = 0; q < 4; ++q) {
                    int u = (q >> 1) * 8 + (tq << 1) + (q & 1);
                    creg[r][rh][q] =
                        c0[(rowbase + r * 16 + rh * 8 + gi) * HID + (ng << 4) + u];
                }
    } else {
#pragma unroll
        for (int r = 0; r < 2; ++r)
#pragma unroll
            for (int rh = 0; rh < 2; ++rh)
#pragma unroll
                for (int q = 0; q < 4; ++q) creg[r][rh][q] = 0.0f;
    }
    const float blin0 = blin[0];

    // ldsm bases: group g2 covers W rows g2*16 .. +15 (n-tiles 2g2, 2g2+1)
    const int m_ = lane >> 3;
    const int r_ = lane & 7;
    const uint32_t s_w = (uint32_t)__cvta_generic_to_shared(ws);
    uint32_t sb[4];
#pragma unroll
    for (int g2 = 0; g2 < 4; ++g2) {
        int wrow = g2 * 16 + ((m_ >> 1) << 3) + r_;
        sb[g2] = s_w + (wrow * KP + ((m_ & 1) << 3)) * 2;
    }

    const int g_rt0  = bg * 4 + rtp * 2;                  // first global rt tile
    const int abase0 = g_rt0 * 8192 + (kq << 4) * 128 + lane * 4;
    const int abase1 = abase0 + 8192;

    grid_barrier(bg);

    // ---------------- time loop ----------------
    for (int t = 0; t < T; ++t) {
        const uint32_t* A = g_frag[t & 1];
        uint32_t* N = g_frag[(t + 1) & 1];

        // acc[r][nb][ci], nb = g*2 + uh, ci = rh*2 + p
        float acc0[8][4], acc1[8][4];
        if (kq == 0) {
            float op[2][2];
            const float* cc = cc0;
            if (t > 0) {
#pragma unroll
                for (int r = 0; r < 2; ++r)
#pragma unroll
                    for (int rh = 0; rh < 2; ++rh)
                        op[r][rh] = __ldcg(
                            &out[(rowbase + r * 16 + rh * 8 + gi) * T + t - 1]);
                cc = cc1;
            } else {
                op[0][0] = op[0][1] = op[1][0] = op[1][1] = 0.0f;
            }
#pragma unroll
            for (int nb = 0; nb < 8; ++nb) {
                int g = nb >> 1, uh = nb & 1;
#pragma unroll
                for (int ci = 0; ci < 4; ++ci) {
                    int p = ci & 1, rh = ci >> 1;
                    int n = g * 16 + uh * 8 + (tq << 1) + p;
                    acc0[nb][ci] = fmaf(op[0][rh], wi0[n], cc[n]);
                    acc1[nb][ci] = fmaf(op[1][rh], wi0[n], cc[n]);
                }
            }
        } else {
#pragma unroll
            for (int nb = 0; nb < 8; ++nb)
#pragma unroll
                for (int ci = 0; ci < 4; ++ci) { acc0[nb][ci] = 0.f; acc1[nb][ci] = 0.f; }
        }

        // GEMM: 16 k-iters, 2 rt tiles share each B load
#pragma unroll 4
        for (int i = 0; i < 16; ++i) {
            uint4 a0 = __ldcg((const uint4*)(A + abase0 + i * 128));
            uint4 a1 = __ldcg((const uint4*)(A + abase1 + i * 128));
            uint32_t so = ((kq << 4) + i) * 32;
#pragma unroll
            for (int g2 = 0; g2 < 4; ++g2) {
                uint32_t b0, b1, b2, b3;
                ldsm_x4(b0, b1, b2, b3, sb[g2] + so);
                mma_f16(acc0[2 * g2],     a0, b0, b1);
                mma_f16(acc0[2 * g2 + 1], a0, b2, b3);
                mma_f16(acc1[2 * g2],     a1, b0, b1);
                mma_f16(acc1[2 * g2 + 1], a1, b2, b3);
            }
        }

        // merge k-quarter partials through SMEM (float4, conflict-free)
        // layout: [rtp][kq-1][r][nb][lane] float4
        if (kq > 0) {
            float* d = red + ((((rtp * 3 + (kq - 1)) * 2) * 8) * 32 + lane) * 4;
#pragma unroll
            for (int nb = 0; nb < 8; ++nb) {
                *(float4*)(d + nb * 128)        = *(float4*)acc0[nb];
                *(float4*)(d + 1024 + nb * 128) = *(float4*)acc1[nb];
            }
        }
        __syncthreads();

        if (kq == 0) {
#pragma unroll
            for (int q = 0; q < 3; ++q) {
                const float* s = red + ((((rtp * 3 + q) * 2) * 8) * 32 + lane) * 4;
#pragma unroll
                for (int nb = 0; nb < 8; ++nb) {
                    float4 x = *(const float4*)(s + nb * 128);
                    float4 y = *(const float4*)(s + 1024 + nb * 128);
                    acc0[nb][0] += x.x; acc0[nb][1] += x.y;
                    acc0[nb][2] += x.z; acc0[nb][3] += x.w;
                    acc1[nb][0] += y.x; acc1[nb][1] += y.y;
                    acc1[nb][2] += y.z; acc1[nb][3] += y.w;
                }
            }

            // pointwise LSTM: gates g for unit (uh,p) at acc[g*2+uh][rh*2+p]
            float hv[2][2][4];
#pragma unroll
            for (int rh = 0; rh < 2; ++rh)
#pragma unroll
                for (int q = 0; q < 4; ++q) {
                    int uh = q >> 1, p = q & 1;
                    int ci = rh * 2 + p;
                    {
                        float cn = fmaf(sigf(acc0[2 + uh][ci]), creg[0][rh][q],
                                        sigf(acc0[0 + uh][ci]) * tanh_f(acc0[4 + uh][ci]));
                        creg[0][rh][q] = cn;
                        hv[0][rh][q] = sigf(acc0[6 + uh][ci]) * tanh_f(cn);
                    }
                    {
                        float cn = fmaf(sigf(acc1[2 + uh][ci]), creg[1][rh][q],
                                        sigf(acc1[0 + uh][ci]) * tanh_f(acc1[4 + uh][ci]));
                        creg[1][rh][q] = cn;
                        hv[1][rh][q] = sigf(acc1[6 + uh][ci]) * tanh_f(cn);
                    }
                }

            // h store: one STG.128 per rt tile
#pragma unroll
            for (int r = 0; r < 2; ++r) {
                uint4 hp;
                hp.x = packh2(hv[r][0][0], hv[r][0][1]);
                hp.y = packh2(hv[r][1][0], hv[r][1][1]);
                hp.z = packh2(hv[r][0][2], hv[r][0][3]);
                hp.w = packh2(hv[r][1][2], hv[r][1][3]);
                *(uint4*)&N[(((g_rt0 + r) * 64 + ng) * 32 + lane) * 4] = hp;
            }

            // scalar head
#pragma unroll
            for (int r = 0; r < 2; ++r)
#pragma unroll
                for (int rh = 0; rh < 2; ++rh) {
                    float acc_s = 0.0f;
#pragma unroll
                    for (int q = 0; q < 4; ++q) {
                        int u = (q >> 1) * 8 + (tq << 1) + (q & 1);
                        acc_s = fmaf(hv[r][rh][q], wl[u], acc_s);
                    }
                    acc_s += __shfl_xor_sync(0xffffffffu, acc_s, 1);
                    acc_s += __shfl_xor_sync(0xffffffffu, acc_s, 2);
                    if (tq == 0) {
                        if (ng == 0) acc_s += blin0;
                        atomicAdd(&out[(rowbase + r * 16 + rh * 8 + gi) * T + t],
                                  acc_s);
                    }
                }
        }

        grid_barrier(bg);
    }
}

extern "C" void kernel_launch(void* const* d_in, const int* in_sizes, int n_in,
                              void* d_out, int out_size) {
    const float* h0   = (const float*)d_in[0];
    const float* c0   = (const float*)d_in[1];
    const float* Wih  = (const float*)d_in[2];
    const float* Whh  = (const float*)d_in[3];
    const float* bih  = (const float*)d_in[4];
    const float* bhh  = (const float*)d_in[5];
    const float* Wlin = (const float*)d_in[6];
    const float* blin = (const float*)d_in[7];
    float* out = (float*)d_out;

    int T = out_size / BSZ;
    if (T <= 0) return;

    cudaFuncSetAttribute(decoder_kernel,
                         cudaFuncAttributeMaxDynamicSharedMemorySize, SMEM_BYTES);
    decoder_kernel<<<NCTA, NTHR, SMEM_BYTES>>>(h0, c0, Wih, Whh, bih, bhh,
                                               Wlin, blin, out, T);
}